// round 13
// baseline (speedup 1.0000x reference)
#include <cuda_runtime.h>

// PLNet expansion: out[pp][n,k,i,j,y,x] =
//   0.5*cor0[ij]*cork[ij] * cen0[yx]*cenk[yx]
//   * cor[23+y][ij] * cor[37+x][ij] * cen[23+i][yx] * cen[37+j][yx]
// cor = corner(pp&1), cen = center(pp>>1).
// Input (n, 204, 14, 14): corner1 ch 0..50, corner2 51..101,
// center1 102..152, center2 153..203.
//
// R11 (best: 67.6 us) + ONE change: __stwt write-through stores
// (vs __stcs evict-first). Pure write-once output stream.
// Block (i-pair {2bx,2bx+1}, n=by, k=bz), i-fastest grid (7,32,20),
// 196 threads = 4 pp x 49 quads.

__global__ __launch_bounds__(196)
void plnet_kernel(const float* __restrict__ in, float* __restrict__ out)
{
    const int i0 = blockIdx.x * 2;  // 0,2,...,12  (fastest dim)
    const int n  = blockIdx.y;      // 0..31
    const int k  = blockIdx.z;      // 0..19
    const int t  = threadIdx.x;

    // W[cc][rij][y] = 0.5*cor0*cork*cor[23+y] ; V[cc][rij][x] = cor[37+x]
    __shared__ float W_s[2 * 28 * 14];
    __shared__ float V_s[2 * 28 * 14];
    __shared__ float a_s[2 * 28];

    const float* nb = in + n * (204 * 196);

    if (t < 56) {
        const int cc  = t / 28;
        const int rij = t - cc * 28;
        const int ij  = i0 * 14 + rij;
        const float* cor = nb + cc * (51 * 196);
        a_s[t] = 0.5f * cor[ij] * cor[(1 + k) * 196 + ij];
    }
    __syncthreads();

    #pragma unroll
    for (int idx = 0; idx < 784; idx += 196) {
        const int id  = idx + t;
        const int rij = id % 28;
        const int tmp = id / 28;
        const int y   = tmp % 14;
        const int cc  = tmp / 14;
        const int ij  = i0 * 14 + rij;
        const float* cor = nb + cc * (51 * 196);
        W_s[cc * 392 + rij * 14 + y] = a_s[cc * 28 + rij] * cor[(23 + y) * 196 + ij];
        V_s[cc * 392 + rij * 14 + y] = cor[(37 + y) * 196 + ij];
    }

    const int pp = t / 49;
    const int q  = t - pp * 49;
    const int cc = pp & 1;
    const int ss = pp >> 1;
    const int e0 = q * 4;           // plane base (y*14+x), 16B aligned
    const int y0 = e0 / 14;
    const int x0 = e0 - y0 * 14;    // even, 0..12

    const float* cen = nb + (102 + ss * 51) * 196;

    const float4 c0 = *(const float4*)(cen + e0);
    const float4 ck = *(const float4*)(cen + (1 + k) * 196 + e0);
    const float bx = c0.x * ck.x, by = c0.y * ck.y, bz = c0.z * ck.z, bw = c0.w * ck.w;

    const bool cross = (x0 == 12);  // elems 2,3 wrap to (y0+1, x=0,1)
    const int vxo = cross ? 0 : x0 + 2;
    const int y1  = cross ? y0 + 1 : y0;

    __syncthreads();

    float* op = out + (size_t)((pp * 32 + n) * 20 + k) * 38416
                    + (size_t)i0 * (14 * 196) + e0;
    const float* Wc = W_s + cc * 392;
    const float* Vc = V_s + cc * 392;

    #pragma unroll
    for (int jb = 0; jb < 14; jb += 7) {
        float4 L[7];
        #pragma unroll
        for (int j = 0; j < 7; ++j)
            L[j] = *(const float4*)(cen + (37 + jb + j) * 196 + e0);

        #pragma unroll
        for (int il = 0; il < 2; ++il) {
            const int i = i0 + il;
            const float4 sx = *(const float4*)(cen + (23 + i) * 196 + e0);
            const float r0 = bx * sx.x, r1 = by * sx.y, r2 = bz * sx.z, r3 = bw * sx.w;

            const float* Wr = Wc + il * 196;
            const float* Vr = Vc + il * 196;
            float* orow = op + (size_t)il * (14 * 196) + (size_t)jb * 196;

            #pragma unroll
            for (int j = 0; j < 7; ++j) {
                const float* wr = Wr + (jb + j) * 14;
                const float* vr = Vr + (jb + j) * 14;
                const float wlo = wr[y0];
                const float whi = wr[y1];
                const float2 vA = *(const float2*)(vr + x0);
                const float2 vB = *(const float2*)(vr + vxo);
                float4 o;
                o.x = (wlo * vA.x) * (r0 * L[j].x);
                o.y = (wlo * vA.y) * (r1 * L[j].y);
                o.z = (whi * vB.x) * (r2 * L[j].z);
                o.w = (whi * vB.y) * (r3 * L[j].w);
                __stwt((float4*)(orow + j * 196), o);
            }
        }
    }
}

extern "C" void kernel_launch(void* const* d_in, const int* in_sizes, int n_in,
                              void* d_out, int out_size)
{
    const float* in = (const float*)d_in[0];
    float* out = (float*)d_out;
    dim3 grid(7, 32, 20);
    plnet_kernel<<<grid, 196>>>(in, out);
}

// round 15
// speedup vs baseline: 1.0616x; 1.0616x over previous
#include <cuda_runtime.h>

// PLNet expansion: out[pp][n,k,i,j,y,x] =
//   0.5*cor0[ij]*cork[ij] * cen0[yx]*cenk[yx]
//   * cor[23+y][ij] * cor[37+x][ij] * cen[23+i][yx] * cen[37+j][yx]
// cor = corner(pp&1), cen = center(pp>>1).
// Input (n, 204, 14, 14): corner1 ch 0..50, corner2 51..101,
// center1 102..152, center2 153..203.
//
// FINAL (R11): i-fastest grid + __stcs evict-first streaming stores.
// Block (i-pair {2bx, 2bx+1}, n=by, k=bz), grid (7,32,20) = 4480 blocks,
// 196 threads = 4 pp x 49 quads; each thread owns an aligned float4 quad
// of the 196-element (y,x) plane -> fully coalesced STG.128.
// cor side in shared (W a-folded, V), cen side register-resident (L[7]).

__global__ __launch_bounds__(196)
void plnet_kernel(const float* __restrict__ in, float* __restrict__ out)
{
    const int i0 = blockIdx.x * 2;  // 0,2,...,12  (fastest dim: contiguous writes)
    const int n  = blockIdx.y;      // 0..31
    const int k  = blockIdx.z;      // 0..19
    const int t  = threadIdx.x;

    // W[cc][rij][y] = 0.5*cor0*cork*cor[23+y] ; V[cc][rij][x] = cor[37+x]
    __shared__ float W_s[2 * 28 * 14];
    __shared__ float V_s[2 * 28 * 14];
    __shared__ float a_s[2 * 28];

    const float* nb = in + n * (204 * 196);

    if (t < 56) {
        const int cc  = t / 28;
        const int rij = t - cc * 28;
        const int ij  = i0 * 14 + rij;
        const float* cor = nb + cc * (51 * 196);
        a_s[t] = 0.5f * cor[ij] * cor[(1 + k) * 196 + ij];
    }
    __syncthreads();

    #pragma unroll
    for (int idx = 0; idx < 784; idx += 196) {
        const int id  = idx + t;
        const int rij = id % 28;
        const int tmp = id / 28;
        const int y   = tmp % 14;
        const int cc  = tmp / 14;
        const int ij  = i0 * 14 + rij;
        const float* cor = nb + cc * (51 * 196);
        W_s[cc * 392 + rij * 14 + y] = a_s[cc * 28 + rij] * cor[(23 + y) * 196 + ij];
        V_s[cc * 392 + rij * 14 + y] = cor[(37 + y) * 196 + ij];
    }

    const int pp = t / 49;
    const int q  = t - pp * 49;
    const int cc = pp & 1;
    const int ss = pp >> 1;
    const int e0 = q * 4;           // plane base (y*14+x), 16B aligned
    const int y0 = e0 / 14;
    const int x0 = e0 - y0 * 14;    // even, 0..12

    const float* cen = nb + (102 + ss * 51) * 196;

    const float4 c0 = *(const float4*)(cen + e0);
    const float4 ck = *(const float4*)(cen + (1 + k) * 196 + e0);
    const float bx = c0.x * ck.x, by = c0.y * ck.y, bz = c0.z * ck.z, bw = c0.w * ck.w;

    const bool cross = (x0 == 12);  // elems 2,3 wrap to (y0+1, x=0,1)
    const int vxo = cross ? 0 : x0 + 2;
    const int y1  = cross ? y0 + 1 : y0;

    __syncthreads();

    float* op = out + (size_t)((pp * 32 + n) * 20 + k) * 38416
                    + (size_t)i0 * (14 * 196) + e0;
    const float* Wc = W_s + cc * 392;
    const float* Vc = V_s + cc * 392;

    #pragma unroll
    for (int jb = 0; jb < 14; jb += 7) {
        float4 L[7];
        #pragma unroll
        for (int j = 0; j < 7; ++j)
            L[j] = *(const float4*)(cen + (37 + jb + j) * 196 + e0);

        #pragma unroll
        for (int il = 0; il < 2; ++il) {
            const int i = i0 + il;
            const float4 sx = *(const float4*)(cen + (23 + i) * 196 + e0);
            const float r0 = bx * sx.x, r1 = by * sx.y, r2 = bz * sx.z, r3 = bw * sx.w;

            const float* Wr = Wc + il * 196;
            const float* Vr = Vc + il * 196;
            float* orow = op + (size_t)il * (14 * 196) + (size_t)jb * 196;

            #pragma unroll
            for (int j = 0; j < 7; ++j) {
                const float* wr = Wr + (jb + j) * 14;
                const float* vr = Vr + (jb + j) * 14;
                const float wlo = wr[y0];
                const float whi = wr[y1];
                const float2 vA = *(const float2*)(vr + x0);
                const float2 vB = *(const float2*)(vr + vxo);
                float4 o;
                o.x = (wlo * vA.x) * (r0 * L[j].x);
                o.y = (wlo * vA.y) * (r1 * L[j].y);
                o.z = (whi * vB.x) * (r2 * L[j].z);
                o.w = (whi * vB.y) * (r3 * L[j].w);
                __stcs((float4*)(orow + j * 196), o);
            }
        }
    }
}

extern "C" void kernel_launch(void* const* d_in, const int* in_sizes, int n_in,
                              void* d_out, int out_size)
{
    const float* in = (const float*)d_in[0];
    float* out = (float*)d_out;
    dim3 grid(7, 32, 20);
    plnet_kernel<<<grid, 196>>>(in, out);
}

// round 16
// speedup vs baseline: 1.0621x; 1.0005x over previous
#include <cuda_runtime.h>

// PLNet expansion: out[pp][n,k,i,j,y,x] =
//   0.5*cor0[ij]*cork[ij] * cen0[yx]*cenk[yx]
//   * cor[23+y][ij] * cor[37+x][ij] * cen[23+i][yx] * cen[37+j][yx]
// cor = corner(pp&1), cen = center(pp>>1).
// Input (n, 204, 14, 14): corner1 ch 0..50, corner2 51..101,
// center1 102..152, center2 153..203.
//
// R11 body + grid permuted (i, k, n): i fastest, k second -> each run of
// 7*20 = 140 consecutive blocks writes one fully CONTIGUOUS 21.5 MB output
// region per pp (k regions tile seamlessly after i regions; the 3 MB
// n-stride jump now happens only every 140 blocks instead of every 7).
// Block (i-pair {2bx, 2bx+1}, k=by, n=bz), 196 threads = 4 pp x 49 quads,
// aligned float4 quads -> coalesced STG.128, __stcs evict-first stores.

__global__ __launch_bounds__(196)
void plnet_kernel(const float* __restrict__ in, float* __restrict__ out)
{
    const int i0 = blockIdx.x * 2;  // 0,2,...,12  (fastest dim)
    const int k  = blockIdx.y;      // 0..19       (second: contiguous after i)
    const int n  = blockIdx.z;      // 0..31
    const int t  = threadIdx.x;

    // W[cc][rij][y] = 0.5*cor0*cork*cor[23+y] ; V[cc][rij][x] = cor[37+x]
    __shared__ float W_s[2 * 28 * 14];
    __shared__ float V_s[2 * 28 * 14];
    __shared__ float a_s[2 * 28];

    const float* nb = in + n * (204 * 196);

    if (t < 56) {
        const int cc  = t / 28;
        const int rij = t - cc * 28;
        const int ij  = i0 * 14 + rij;
        const float* cor = nb + cc * (51 * 196);
        a_s[t] = 0.5f * cor[ij] * cor[(1 + k) * 196 + ij];
    }
    __syncthreads();

    #pragma unroll
    for (int idx = 0; idx < 784; idx += 196) {
        const int id  = idx + t;
        const int rij = id % 28;
        const int tmp = id / 28;
        const int y   = tmp % 14;
        const int cc  = tmp / 14;
        const int ij  = i0 * 14 + rij;
        const float* cor = nb + cc * (51 * 196);
        W_s[cc * 392 + rij * 14 + y] = a_s[cc * 28 + rij] * cor[(23 + y) * 196 + ij];
        V_s[cc * 392 + rij * 14 + y] = cor[(37 + y) * 196 + ij];
    }

    const int pp = t / 49;
    const int q  = t - pp * 49;
    const int cc = pp & 1;
    const int ss = pp >> 1;
    const int e0 = q * 4;           // plane base (y*14+x), 16B aligned
    const int y0 = e0 / 14;
    const int x0 = e0 - y0 * 14;    // even, 0..12

    const float* cen = nb + (102 + ss * 51) * 196;

    const float4 c0 = *(const float4*)(cen + e0);
    const float4 ck = *(const float4*)(cen + (1 + k) * 196 + e0);
    const float bx = c0.x * ck.x, by = c0.y * ck.y, bz = c0.z * ck.z, bw = c0.w * ck.w;

    const bool cross = (x0 == 12);  // elems 2,3 wrap to (y0+1, x=0,1)
    const int vxo = cross ? 0 : x0 + 2;
    const int y1  = cross ? y0 + 1 : y0;

    __syncthreads();

    float* op = out + (size_t)((pp * 32 + n) * 20 + k) * 38416
                    + (size_t)i0 * (14 * 196) + e0;
    const float* Wc = W_s + cc * 392;
    const float* Vc = V_s + cc * 392;

    #pragma unroll
    for (int jb = 0; jb < 14; jb += 7) {
        float4 L[7];
        #pragma unroll
        for (int j = 0; j < 7; ++j)
            L[j] = *(const float4*)(cen + (37 + jb + j) * 196 + e0);

        #pragma unroll
        for (int il = 0; il < 2; ++il) {
            const int i = i0 + il;
            const float4 sx = *(const float4*)(cen + (23 + i) * 196 + e0);
            const float r0 = bx * sx.x, r1 = by * sx.y, r2 = bz * sx.z, r3 = bw * sx.w;

            const float* Wr = Wc + il * 196;
            const float* Vr = Vc + il * 196;
            float* orow = op + (size_t)il * (14 * 196) + (size_t)jb * 196;

            #pragma unroll
            for (int j = 0; j < 7; ++j) {
                const float* wr = Wr + (jb + j) * 14;
                const float* vr = Vr + (jb + j) * 14;
                const float wlo = wr[y0];
                const float whi = wr[y1];
                const float2 vA = *(const float2*)(vr + x0);
                const float2 vB = *(const float2*)(vr + vxo);
                float4 o;
                o.x = (wlo * vA.x) * (r0 * L[j].x);
                o.y = (wlo * vA.y) * (r1 * L[j].y);
                o.z = (whi * vB.x) * (r2 * L[j].z);
                o.w = (whi * vB.y) * (r3 * L[j].w);
                __stcs((float4*)(orow + j * 196), o);
            }
        }
    }
}

extern "C" void kernel_launch(void* const* d_in, const int* in_sizes, int n_in,
                              void* d_out, int out_size)
{
    const float* in = (const float*)d_in[0];
    float* out = (float*)d_out;
    dim3 grid(7, 20, 32);
    plnet_kernel<<<grid, 196>>>(in, out);
}